// round 3
// baseline (speedup 1.0000x reference)
#include <cuda_runtime.h>

// HashEmbedder: 16-level multires hash grid, F=2, IN_DIM=3, K=8 corners.
// Levels 0..5 dense (row-major), 6..15 hashed (XOR-prime, mod 524309).
// Grid split: dense region = one thread per (point, level 0..5),
//             hash region  = one thread per (point, level 6..15).
// Hash gathers use ld.global.cg (L2-only) so the 42MB always-miss hash stream
// does not allocate/fill L1; dense tables (coarse levels reused ~1000x) stay
// L1-resident via __ldg.

#define T_HASH 524309ULL
// Barrett magic: floor(2^64/T)+1. Exact for n < 2^38 (error term < 2^-45).
#define BARRETT_M ((0xFFFFFFFFFFFFFFFFULL / T_HASH) + 1ULL)

__device__ __forceinline__ unsigned int mod_T(unsigned long long n) {
    unsigned long long q = __umul64hi(n, BARRETT_M);
    return (unsigned int)(n - q * T_HASH);
}

// L2-only gather (no L1 allocation). Non-volatile asm: pure load, reorderable.
__device__ __forceinline__ float2 ldcg2(const float2* __restrict__ p) {
    float2 v;
    asm("ld.global.cg.v2.f32 {%0,%1}, [%2];" : "=f"(v.x), "=f"(v.y) : "l"(p));
    return v;
}

// Per-level resolutions: int(16 * 1.38^i). All >0.04 from integer boundaries.
__device__ const int g_n[16] = {16,22,30,42,58,80,110,152,210,290,400,553,763,1053,1453,2005};
// ENTRIES_SIZE = float32(1.0/(n-1)) — same double->float rounding as numpy.
__device__ const float g_es[16] = {
    (float)(1.0/15.0),   (float)(1.0/21.0),   (float)(1.0/29.0),   (float)(1.0/41.0),
    (float)(1.0/57.0),   (float)(1.0/79.0),   (float)(1.0/109.0),  (float)(1.0/151.0),
    (float)(1.0/209.0),  (float)(1.0/289.0),  (float)(1.0/399.0),  (float)(1.0/552.0),
    (float)(1.0/762.0),  (float)(1.0/1052.0), (float)(1.0/1452.0), (float)(1.0/2004.0)};
// cumsum of n^3 for dense levels
__device__ const int g_base[6] = {0, 4096, 14744, 41744, 115832, 310944};

// Load corners j=ja and j=jb (jb == ja or ja+1) from the dense table viewed as
// float4 (16B loads never split a 32B sector; even ja -> one load covers both
// corners). Returns v[ja] + v[jb]. L1-cached: dense tables have heavy reuse.
__device__ __forceinline__ float2 dense_pair_sum(const float4* __restrict__ d4,
                                                 int ja, int jb) {
    int ka = ja >> 1, kb = jb >> 1;
    float4 qa = __ldg(d4 + ka);
    float4 qb = qa;
    if (kb != ka) qb = __ldg(d4 + kb);   // small body -> predicated @P LDG
    float lox = (ja & 1) ? qa.z : qa.x;
    float loy = (ja & 1) ? qa.w : qa.y;
    float hix = (jb & 1) ? qb.z : qb.x;
    float hiy = (jb & 1) ? qb.w : qb.y;
    return make_float2(lox + hix, loy + hiy);
}

__global__ void __launch_bounds__(256)
hashenc_kernel(const float* __restrict__ xyz,
               const float* __restrict__ dense,
               const float* __restrict__ hasht,
               float* __restrict__ out,
               int npts, int dense_blocks)
{
    bool is_dense = (int)blockIdx.x < dense_blocks;
    int idx, p, l;
    if (is_dense) {
        idx = blockIdx.x * 256 + threadIdx.x;
        if (idx >= npts * 6) return;
        p = idx / 6;  l = idx - p * 6;          // levels 0..5
    } else {
        idx = (blockIdx.x - dense_blocks) * 256 + threadIdx.x;
        if (idx >= npts * 10) return;
        p = idx / 10; l = 6 + (idx - p * 10);   // levels 6..15
    }

    float x0 = xyz[3 * p + 0];
    float x1 = xyz[3 * p + 1];
    float x2 = xyz[3 * p + 2];

    float* orow = out + (long long)p * 35;
    if (l == 0) {    // include_input passthrough (bounds [0,1] -> identity)
        orow[0] = x0; orow[1] = x1; orow[2] = x2;
    }

    float es  = g_es[l];
    int   nm1 = g_n[l] - 1;

    // flt = x / entries_size (IEEE f32 divide, matching the reference exactly)
    float f0 = __fdiv_rn(x0, es);
    float f1 = __fdiv_rn(x1, es);
    float f2 = __fdiv_rn(x2, es);

    // trunc == floor (flt >= 0); flt+1 exact below 2^23.
    int i0 = (int)f0, i1 = (int)f1, i2 = (int)f2;
    int a0 = min(i0, nm1),     a1 = min(i1, nm1),     a2 = min(i2, nm1);
    int b0 = min(i0 + 1, nm1), b1 = min(i1 + 1, nm1), b2 = min(i2 + 1, nm1);

    // fractional offset from corner 0; weights use dims 0,1 only (as in source)
    float o0 = f0 - (float)a0;
    float o1 = f1 - (float)a1;
    float u0 = 1.0f - o0, u1 = 1.0f - o1;
    float w00 = u0 * u1, w01 = u0 * o1, w10 = o0 * u1, w11 = o0 * o1;

    float2 s00, s01, s10, s11;   // per-(dim0,dim1) corner pair sums over dim2

    if (is_dense) {
        const float4* d4 = (const float4*)dense;
        int n  = nm1 + 1;
        int s1 = n, s0 = n * n;
        int base = g_base[l];
        int A0 = a0 * s0 + base, B0 = b0 * s0 + base;
        int A1 = a1 * s1,        B1 = b1 * s1;
        s00 = dense_pair_sum(d4, A0 + A1 + a2, A0 + A1 + b2);
        s01 = dense_pair_sum(d4, A0 + B1 + a2, A0 + B1 + b2);
        s10 = dense_pair_sum(d4, B0 + A1 + a2, B0 + A1 + b2);
        s11 = dense_pair_sum(d4, B0 + B1 + a2, B0 + B1 + b2);
    } else {
        const float2* h2 = (const float2*)hasht + (unsigned long long)(l - 6) * T_HASH;
        // ih = 1 ^ (x0*1) ^ (x1*19349663) ^ (x2*83492791), then % T
        unsigned long long A0h = 1ULL ^ (unsigned long long)(unsigned)a0;
        unsigned long long B0h = 1ULL ^ (unsigned long long)(unsigned)b0;
        unsigned long long A1h = (unsigned long long)(unsigned)a1 * 19349663ULL;
        unsigned long long B1h = (unsigned long long)(unsigned)b1 * 19349663ULL;
        unsigned long long A2h = (unsigned long long)(unsigned)a2 * 83492791ULL;
        unsigned long long B2h = (unsigned long long)(unsigned)b2 * 83492791ULL;
        float2 v0 = ldcg2(h2 + mod_T(A0h ^ A1h ^ A2h));
        float2 v1 = ldcg2(h2 + mod_T(A0h ^ A1h ^ B2h));
        float2 v2 = ldcg2(h2 + mod_T(A0h ^ B1h ^ A2h));
        float2 v3 = ldcg2(h2 + mod_T(A0h ^ B1h ^ B2h));
        float2 v4 = ldcg2(h2 + mod_T(B0h ^ A1h ^ A2h));
        float2 v5 = ldcg2(h2 + mod_T(B0h ^ A1h ^ B2h));
        float2 v6 = ldcg2(h2 + mod_T(B0h ^ B1h ^ A2h));
        float2 v7 = ldcg2(h2 + mod_T(B0h ^ B1h ^ B2h));
        s00 = make_float2(v0.x + v1.x, v0.y + v1.y);
        s01 = make_float2(v2.x + v3.x, v2.y + v3.y);
        s10 = make_float2(v4.x + v5.x, v4.y + v5.y);
        s11 = make_float2(v6.x + v7.x, v6.y + v7.y);
    }

    float rx = w00 * s00.x + w01 * s01.x + w10 * s10.x + w11 * s11.x;
    float ry = w00 * s00.y + w01 * s01.y + w10 * s10.y + w11 * s11.y;

    orow[3 + 2 * l] = rx;
    orow[4 + 2 * l] = ry;
}

extern "C" void kernel_launch(void* const* d_in, const int* in_sizes, int n_in,
                              void* d_out, int out_size) {
    const float* xyz   = (const float*)d_in[0];   // (2,65536,3) f32
    const float* dense = (const float*)d_in[1];   // (822944,2) f32
    const float* hasht = (const float*)d_in[2];   // (10,524309,2) f32
    float* out = (float*)d_out;                   // (2,65536,35) f32

    int npts = in_sizes[0] / 3;
    int dense_blocks = (npts * 6 + 255) / 256;
    int hash_blocks  = (npts * 10 + 255) / 256;
    hashenc_kernel<<<dense_blocks + hash_blocks, 256>>>(xyz, dense, hasht, out,
                                                        npts, dense_blocks);
}

// round 7
// speedup vs baseline: 1.0337x; 1.0337x over previous
#include <cuda_runtime.h>

// HashEmbedder: 16-level multires hash grid, F=2, IN_DIM=3, K=8 corners.
// Levels 0..1 dense, staged in SMEM (14744 entries = 118KB) -> gathers served
// by the (otherwise idle) LDS crossbar instead of the saturated L1tex pipe.
// Levels 2..5 dense via __ldg; levels 6..15 hashed via __ldg (L1 hits matter:
// the .cg experiment regressed). Persistent grid: 148 blocks x 1024 threads,
// stage once per block, grid-stride over all (point, level) items.

#define T_HASH 524309ULL
// Barrett magic: floor(2^64/T)+1. Exact for n < 2^38 (error term < 2^-45).
#define BARRETT_M ((0xFFFFFFFFFFFFFFFFULL / T_HASH) + 1ULL)

#define SMEM_ENTRIES 14744            // level0 (16^3=4096) + level1 (22^3=10648)
#define SMEM_BYTES   (SMEM_ENTRIES * 8)

__device__ __forceinline__ unsigned int mod_T(unsigned long long n) {
    unsigned long long q = __umul64hi(n, BARRETT_M);
    return (unsigned int)(n - q * T_HASH);
}

// Per-level resolutions: int(16 * 1.38^i). All >0.04 from integer boundaries.
__device__ const int g_n[16] = {16,22,30,42,58,80,110,152,210,290,400,553,763,1053,1453,2005};
// ENTRIES_SIZE = float32(1.0/(n-1)) — same double->float rounding as numpy.
__device__ const float g_es[16] = {
    (float)(1.0/15.0),   (float)(1.0/21.0),   (float)(1.0/29.0),   (float)(1.0/41.0),
    (float)(1.0/57.0),   (float)(1.0/79.0),   (float)(1.0/109.0),  (float)(1.0/151.0),
    (float)(1.0/209.0),  (float)(1.0/289.0),  (float)(1.0/399.0),  (float)(1.0/552.0),
    (float)(1.0/762.0),  (float)(1.0/1052.0), (float)(1.0/1452.0), (float)(1.0/2004.0)};
// cumsum of n^3 for dense levels
__device__ const int g_base[6] = {0, 4096, 14744, 41744, 115832, 310944};

__global__ void __launch_bounds__(1024, 1)
hashenc_kernel(const float* __restrict__ xyz,
               const float* __restrict__ dense,
               const float* __restrict__ hasht,
               float* __restrict__ out,
               int npts)
{
    extern __shared__ float2 s_tab[];   // levels 0+1, linear layout (base 0 / 4096)

    // Stage levels 0..1 into SMEM, coalesced float4 copy (7372 x 16B).
    {
        const float4* d4 = (const float4*)dense;
        float4* s4 = (float4*)s_tab;
        #pragma unroll 4
        for (int i = threadIdx.x; i < SMEM_ENTRIES / 2; i += 1024)
            s4[i] = __ldg(d4 + i);
    }
    __syncthreads();

    int total  = npts * 16;
    int stride = gridDim.x * 1024;

    for (int idx = blockIdx.x * 1024 + threadIdx.x; idx < total; idx += stride) {
        int p = idx >> 4;        // point
        int l = idx & 15;        // level

        float x0 = __ldg(xyz + 3 * p + 0);
        float x1 = __ldg(xyz + 3 * p + 1);
        float x2 = __ldg(xyz + 3 * p + 2);

        float* orow = out + (long long)p * 35;
        if (l == 0) {            // include_input passthrough (bounds [0,1])
            orow[0] = x0; orow[1] = x1; orow[2] = x2;
        }

        float es  = g_es[l];
        int   nm1 = g_n[l] - 1;

        // flt = x / entries_size (IEEE f32 divide, matching reference exactly)
        float f0 = __fdiv_rn(x0, es);
        float f1 = __fdiv_rn(x1, es);
        float f2 = __fdiv_rn(x2, es);

        // trunc == floor (flt >= 0); flt+1 exact below 2^23.
        int i0 = (int)f0, i1 = (int)f1, i2 = (int)f2;
        int a0 = min(i0, nm1),     a1 = min(i1, nm1),     a2 = min(i2, nm1);
        int b0 = min(i0 + 1, nm1), b1 = min(i1 + 1, nm1), b2 = min(i2 + 1, nm1);

        // fractional offset from corner 0; weights use dims 0,1 only (as in source)
        float o0 = f0 - (float)a0;
        float o1 = f1 - (float)a1;
        float u0 = 1.0f - o0, u1 = 1.0f - o1;
        float w00 = u0 * u1, w01 = u0 * o1, w10 = o0 * u1, w11 = o0 * o1;

        float2 v0, v1, v2, v3, v4, v5, v6, v7;

        if (l < 6) {
            int n  = nm1 + 1;
            int s1 = n, s0 = n * n;
            int base = g_base[l];
            int A0 = a0 * s0 + base, B0 = b0 * s0 + base;
            int A1 = a1 * s1,        B1 = b1 * s1;
            if (l < 2) {            // SMEM-resident levels -> LDS gathers
                v0 = s_tab[A0 + A1 + a2];
                v1 = s_tab[A0 + A1 + b2];
                v2 = s_tab[A0 + B1 + a2];
                v3 = s_tab[A0 + B1 + b2];
                v4 = s_tab[B0 + A1 + a2];
                v5 = s_tab[B0 + A1 + b2];
                v6 = s_tab[B0 + B1 + a2];
                v7 = s_tab[B0 + B1 + b2];
            } else {
                const float2* d2 = (const float2*)dense;
                v0 = __ldg(d2 + (A0 + A1 + a2));
                v1 = __ldg(d2 + (A0 + A1 + b2));
                v2 = __ldg(d2 + (A0 + B1 + a2));
                v3 = __ldg(d2 + (A0 + B1 + b2));
                v4 = __ldg(d2 + (B0 + A1 + a2));
                v5 = __ldg(d2 + (B0 + A1 + b2));
                v6 = __ldg(d2 + (B0 + B1 + a2));
                v7 = __ldg(d2 + (B0 + B1 + b2));
            }
        } else {
            const float2* h2 = (const float2*)hasht + (unsigned long long)(l - 6) * T_HASH;
            // ih = 1 ^ (x0*1) ^ (x1*19349663) ^ (x2*83492791), then % T
            unsigned long long A0h = 1ULL ^ (unsigned long long)(unsigned)a0;
            unsigned long long B0h = 1ULL ^ (unsigned long long)(unsigned)b0;
            unsigned long long A1h = (unsigned long long)(unsigned)a1 * 19349663ULL;
            unsigned long long B1h = (unsigned long long)(unsigned)b1 * 19349663ULL;
            unsigned long long A2h = (unsigned long long)(unsigned)a2 * 83492791ULL;
            unsigned long long B2h = (unsigned long long)(unsigned)b2 * 83492791ULL;
            v0 = __ldg(h2 + mod_T(A0h ^ A1h ^ A2h));
            v1 = __ldg(h2 + mod_T(A0h ^ A1h ^ B2h));
            v2 = __ldg(h2 + mod_T(A0h ^ B1h ^ A2h));
            v3 = __ldg(h2 + mod_T(A0h ^ B1h ^ B2h));
            v4 = __ldg(h2 + mod_T(B0h ^ A1h ^ A2h));
            v5 = __ldg(h2 + mod_T(B0h ^ A1h ^ B2h));
            v6 = __ldg(h2 + mod_T(B0h ^ B1h ^ A2h));
            v7 = __ldg(h2 + mod_T(B0h ^ B1h ^ B2h));
        }

        float rx = w00 * (v0.x + v1.x) + w01 * (v2.x + v3.x)
                 + w10 * (v4.x + v5.x) + w11 * (v6.x + v7.x);
        float ry = w00 * (v0.y + v1.y) + w01 * (v2.y + v3.y)
                 + w10 * (v4.y + v5.y) + w11 * (v6.y + v7.y);

        orow[3 + 2 * l] = rx;
        orow[4 + 2 * l] = ry;
    }
}

extern "C" void kernel_launch(void* const* d_in, const int* in_sizes, int n_in,
                              void* d_out, int out_size) {
    const float* xyz   = (const float*)d_in[0];   // (2,65536,3) f32
    const float* dense = (const float*)d_in[1];   // (822944,2) f32
    const float* hasht = (const float*)d_in[2];   // (10,524309,2) f32
    float* out = (float*)d_out;                   // (2,65536,35) f32

    int npts = in_sizes[0] / 3;

    cudaFuncSetAttribute(hashenc_kernel,
                         cudaFuncAttributeMaxDynamicSharedMemorySize, SMEM_BYTES);
    hashenc_kernel<<<148, 1024, SMEM_BYTES>>>(xyz, dense, hasht, out, npts);
}

// round 8
// speedup vs baseline: 1.1138x; 1.0774x over previous
#include <cuda_runtime.h>

// HashEmbedder: 16-level multires hash grid, F=2, IN_DIM=3, K=8 corners.
// Levels 0..5 dense (row-major), 6..15 hashed (XOR-prime, mod 524309).
// R1 mapping (best measured): one thread per (point, level), levels interleaved
// within a warp -> partially-masked LDGs with low within-instruction divergence.
// Added: dense dim2 corner pairs loaded as one float4 when sector-aligned
// (weights ignore dim2, so the pair is summed anyway) -> ~9% fewer sectors.

#define T_HASH 524309ULL
// Barrett magic: floor(2^64/T)+1. Exact for n < 2^38 (error term < 2^-45).
#define BARRETT_M ((0xFFFFFFFFFFFFFFFFULL / T_HASH) + 1ULL)

__device__ __forceinline__ unsigned int mod_T(unsigned long long n) {
    unsigned long long q = __umul64hi(n, BARRETT_M);
    return (unsigned int)(n - q * T_HASH);
}

// Per-level resolutions: int(16 * 1.38^i). All >0.04 from integer boundaries.
__device__ const int g_n[16] = {16,22,30,42,58,80,110,152,210,290,400,553,763,1053,1453,2005};
// ENTRIES_SIZE = float32(1.0/(n-1)) — same double->float rounding as numpy.
__device__ const float g_es[16] = {
    (float)(1.0/15.0),   (float)(1.0/21.0),   (float)(1.0/29.0),   (float)(1.0/41.0),
    (float)(1.0/57.0),   (float)(1.0/79.0),   (float)(1.0/109.0),  (float)(1.0/151.0),
    (float)(1.0/209.0),  (float)(1.0/289.0),  (float)(1.0/399.0),  (float)(1.0/552.0),
    (float)(1.0/762.0),  (float)(1.0/1052.0), (float)(1.0/1452.0), (float)(1.0/2004.0)};
// cumsum of n^3 for dense levels
__device__ const int g_base[6] = {0, 4096, 14744, 41744, 115832, 310944};

// Sum of corners j=ja and j=jb (jb == ja+1, or ja when clipped) from the dense
// table viewed as float4. A 16B-aligned float4 never splits a 32B sector, and
// when ja is even one load covers both corners -> expected 1.5 sectors/pair
// instead of 2. When ka==kb the second LDG is predicated off.
__device__ __forceinline__ float2 dense_pair_sum(const float4* __restrict__ d4,
                                                 int ja, int jb) {
    int ka = ja >> 1, kb = jb >> 1;
    float4 qa = __ldg(d4 + ka);
    float4 qb = qa;
    if (kb != ka) qb = __ldg(d4 + kb);   // small body -> predicated @P LDG
    float lox = (ja & 1) ? qa.z : qa.x;
    float loy = (ja & 1) ? qa.w : qa.y;
    float hix = (jb & 1) ? qb.z : qb.x;
    float hiy = (jb & 1) ? qb.w : qb.y;
    return make_float2(lox + hix, loy + hiy);
}

__global__ void __launch_bounds__(256)
hashenc_kernel(const float* __restrict__ xyz,
               const float* __restrict__ dense,
               const float* __restrict__ hasht,
               float* __restrict__ out,
               int npts)
{
    int idx = blockIdx.x * 256 + threadIdx.x;
    int p = idx >> 4;        // point
    if (p >= npts) return;
    int l = idx & 15;        // level

    float x0 = xyz[3 * p + 0];
    float x1 = xyz[3 * p + 1];
    float x2 = xyz[3 * p + 2];

    float* orow = out + (long long)p * 35;
    if (l == 0) {            // include_input passthrough (bounds [0,1] -> identity)
        orow[0] = x0; orow[1] = x1; orow[2] = x2;
    }

    float es  = g_es[l];
    int   nm1 = g_n[l] - 1;

    // flt = x / entries_size  (IEEE f32 divide, matching the reference exactly)
    float f0 = __fdiv_rn(x0, es);
    float f1 = __fdiv_rn(x1, es);
    float f2 = __fdiv_rn(x2, es);

    // trunc == floor (flt >= 0); flt+1 exact below 2^23.
    int i0 = (int)f0, i1 = (int)f1, i2 = (int)f2;
    int a0 = min(i0, nm1),     a1 = min(i1, nm1),     a2 = min(i2, nm1);
    int b0 = min(i0 + 1, nm1), b1 = min(i1 + 1, nm1), b2 = min(i2 + 1, nm1);

    // fractional offset from corner 0; weights use dims 0,1 only (as in source)
    float o0 = f0 - (float)a0;
    float o1 = f1 - (float)a1;
    float u0 = 1.0f - o0, u1 = 1.0f - o1;
    float w00 = u0 * u1, w01 = u0 * o1, w10 = o0 * u1, w11 = o0 * o1;

    float2 s00, s01, s10, s11;   // per-(dim0,dim1) corner-pair sums over dim2

    if (l < 6) {
        const float4* d4 = (const float4*)dense;
        int n  = nm1 + 1;
        int s1 = n, s0 = n * n;
        int base = g_base[l];
        int A0 = a0 * s0 + base, B0 = b0 * s0 + base;
        int A1 = a1 * s1,        B1 = b1 * s1;
        s00 = dense_pair_sum(d4, A0 + A1 + a2, A0 + A1 + b2);
        s01 = dense_pair_sum(d4, A0 + B1 + a2, A0 + B1 + b2);
        s10 = dense_pair_sum(d4, B0 + A1 + a2, B0 + A1 + b2);
        s11 = dense_pair_sum(d4, B0 + B1 + a2, B0 + B1 + b2);
    } else {
        const float2* h2 = (const float2*)hasht + (unsigned long long)(l - 6) * T_HASH;
        // ih = 1 ^ (x0*1) ^ (x1*19349663) ^ (x2*83492791), then % T
        unsigned long long A0h = 1ULL ^ (unsigned long long)(unsigned)a0;
        unsigned long long B0h = 1ULL ^ (unsigned long long)(unsigned)b0;
        unsigned long long A1h = (unsigned long long)(unsigned)a1 * 19349663ULL;
        unsigned long long B1h = (unsigned long long)(unsigned)b1 * 19349663ULL;
        unsigned long long A2h = (unsigned long long)(unsigned)a2 * 83492791ULL;
        unsigned long long B2h = (unsigned long long)(unsigned)b2 * 83492791ULL;
        float2 v0 = __ldg(h2 + mod_T(A0h ^ A1h ^ A2h));
        float2 v1 = __ldg(h2 + mod_T(A0h ^ A1h ^ B2h));
        float2 v2 = __ldg(h2 + mod_T(A0h ^ B1h ^ A2h));
        float2 v3 = __ldg(h2 + mod_T(A0h ^ B1h ^ B2h));
        float2 v4 = __ldg(h2 + mod_T(B0h ^ A1h ^ A2h));
        float2 v5 = __ldg(h2 + mod_T(B0h ^ A1h ^ B2h));
        float2 v6 = __ldg(h2 + mod_T(B0h ^ B1h ^ A2h));
        float2 v7 = __ldg(h2 + mod_T(B0h ^ B1h ^ B2h));
        s00 = make_float2(v0.x + v1.x, v0.y + v1.y);
        s01 = make_float2(v2.x + v3.x, v2.y + v3.y);
        s10 = make_float2(v4.x + v5.x, v4.y + v5.y);
        s11 = make_float2(v6.x + v7.x, v6.y + v7.y);
    }

    float rx = w00 * s00.x + w01 * s01.x + w10 * s10.x + w11 * s11.x;
    float ry = w00 * s00.y + w01 * s01.y + w10 * s10.y + w11 * s11.y;

    orow[3 + 2 * l] = rx;
    orow[4 + 2 * l] = ry;
}

extern "C" void kernel_launch(void* const* d_in, const int* in_sizes, int n_in,
                              void* d_out, int out_size) {
    const float* xyz   = (const float*)d_in[0];   // (2,65536,3) f32
    const float* dense = (const float*)d_in[1];   // (822944,2) f32
    const float* hasht = (const float*)d_in[2];   // (10,524309,2) f32
    float* out = (float*)d_out;                   // (2,65536,35) f32

    int npts = in_sizes[0] / 3;
    int total = npts * 16;
    int blocks = (total + 255) / 256;
    hashenc_kernel<<<blocks, 256>>>(xyz, dense, hasht, out, npts);
}